// round 17
// baseline (speedup 1.0000x reference)
#include <cuda_runtime.h>
#include <cuda_bf16.h>
#include <cstdint>
#include <cstddef>

// Problem constants
#define B_  256
#define T_  512
#define I_  64
#define H_  256
#define G_  1024            // 4*H
#define BT_ (B_ * T_)       // 131072

// -------- scratch (device globals; no allocation allowed) --------
__device__ float g_xp[(size_t)BT_ * G_];   // gate pre-activations for current layer
__device__ float g_s0[(size_t)BT_ * H_];   // layer output sequence (ping)
__device__ float g_s1[(size_t)BT_ * H_];   // layer output sequence (pong)

// ---------------- packed f32x2 helpers (GEMM kernel) ----------------
__device__ __forceinline__ unsigned long long pack2(float lo, float hi) {
    unsigned long long r;
    asm("mov.b64 %0, {%1, %2};" : "=l"(r)
        : "r"(__float_as_uint(lo)), "r"(__float_as_uint(hi)));
    return r;
}
__device__ __forceinline__ void fma2(unsigned long long& d,
                                     unsigned long long a, unsigned long long b) {
    asm("fma.rn.f32x2 %0, %1, %2, %0;" : "+l"(d) : "l"(a), "l"(b));
}
__device__ __forceinline__ float2 unpack2(unsigned long long v) {
    unsigned lo, hi;
    asm("mov.b64 {%0, %1}, %2;" : "=r"(lo), "=r"(hi) : "l"(v));
    return make_float2(__uint_as_float(lo), __uint_as_float(hi));
}

// =====================================================================
// GEMM v2 (R12-passing): double-buffered, register-prefetch, occ 3.
// (unchanged this round for clean rec attribution)
// =====================================================================
#define APITCH 132
#define BPITCH 68

__global__ void __launch_bounds__(256, 3)
gemm_abt_bias(const float* __restrict__ A, const float* __restrict__ Bm,
              const float* __restrict__ bias1, const float* __restrict__ bias2,
              float* __restrict__ C, int M, int N, int K)
{
    __shared__ float As[2][16 * APITCH];
    __shared__ float Bs[2][16 * BPITCH];

    const int tid = threadIdx.x;
    const int m0  = blockIdx.y * 128;
    const int n0  = blockIdx.x * 64;
    const int ty8 = (tid >> 4) * 8;
    const int tx4 = (tid & 15) * 4;

    const int lm = tid >> 2;
    const int lk = (tid & 3) << 2;

    const float* pA0 = &A[(size_t)(m0 + lm) * K + lk];
    const float* pA1 = &A[(size_t)(m0 + 64 + lm) * K + lk];
    const float* pB  = &Bm[(size_t)(n0 + lm) * K + lk];

    unsigned long long acc2[4][4];
#pragma unroll
    for (int p = 0; p < 4; ++p)
#pragma unroll
        for (int j = 0; j < 4; ++j) acc2[p][j] = 0ULL;

    const int ntile = K >> 4;

    float4 ra0 = *(const float4*)pA0;
    float4 ra1 = *(const float4*)pA1;
    float4 rb  = *(const float4*)pB;
    {
        float* as = As[0];
        float* bs = Bs[0];
        as[(lk + 0) * APITCH + lm]      = ra0.x;
        as[(lk + 1) * APITCH + lm]      = ra0.y;
        as[(lk + 2) * APITCH + lm]      = ra0.z;
        as[(lk + 3) * APITCH + lm]      = ra0.w;
        as[(lk + 0) * APITCH + 64 + lm] = ra1.x;
        as[(lk + 1) * APITCH + 64 + lm] = ra1.y;
        as[(lk + 2) * APITCH + 64 + lm] = ra1.z;
        as[(lk + 3) * APITCH + 64 + lm] = ra1.w;
        bs[(lk + 0) * BPITCH + lm] = rb.x;
        bs[(lk + 1) * BPITCH + lm] = rb.y;
        bs[(lk + 2) * BPITCH + lm] = rb.z;
        bs[(lk + 3) * BPITCH + lm] = rb.w;
    }
    __syncthreads();

    for (int kt = 0; kt < ntile; ++kt) {
        const bool more = (kt + 1) < ntile;
        if (more) {
            int off = (kt + 1) << 4;
            ra0 = *(const float4*)(pA0 + off);
            ra1 = *(const float4*)(pA1 + off);
            rb  = *(const float4*)(pB  + off);
        }

        const float* as = As[kt & 1];
        const float* bs = Bs[kt & 1];
#pragma unroll
        for (int kk = 0; kk < 16; ++kk) {
            ulonglong2 a01 = *(const ulonglong2*)&as[kk * APITCH + ty8];
            ulonglong2 a23 = *(const ulonglong2*)&as[kk * APITCH + ty8 + 4];
            float4 bv = *(const float4*)&bs[kk * BPITCH + tx4];
            unsigned long long am[4] = {a01.x, a01.y, a23.x, a23.y};
            float br[4] = {bv.x, bv.y, bv.z, bv.w};
#pragma unroll
            for (int j = 0; j < 4; ++j) {
                unsigned long long bp = pack2(br[j], br[j]);
#pragma unroll
                for (int p = 0; p < 4; ++p) fma2(acc2[p][j], am[p], bp);
            }
        }

        if (more) {
            float* asn = As[(kt + 1) & 1];
            float* bsn = Bs[(kt + 1) & 1];
            asn[(lk + 0) * APITCH + lm]      = ra0.x;
            asn[(lk + 1) * APITCH + lm]      = ra0.y;
            asn[(lk + 2) * APITCH + lm]      = ra0.z;
            asn[(lk + 3) * APITCH + lm]      = ra0.w;
            asn[(lk + 0) * APITCH + 64 + lm] = ra1.x;
            asn[(lk + 1) * APITCH + 64 + lm] = ra1.y;
            asn[(lk + 2) * APITCH + 64 + lm] = ra1.z;
            asn[(lk + 3) * APITCH + 64 + lm] = ra1.w;
            bsn[(lk + 0) * BPITCH + lm] = rb.x;
            bsn[(lk + 1) * BPITCH + lm] = rb.y;
            bsn[(lk + 2) * BPITCH + lm] = rb.z;
            bsn[(lk + 3) * BPITCH + lm] = rb.w;
            __syncthreads();
        }
    }

    float bvv[4];
#pragma unroll
    for (int j = 0; j < 4; ++j) {
        float b = bias1[n0 + tx4 + j];
        if (bias2) b += bias2[n0 + tx4 + j];
        bvv[j] = b;
    }
#pragma unroll
    for (int p = 0; p < 4; ++p) {
        float4 o0, o1;
        float2 u0 = unpack2(acc2[p][0]);
        float2 u1 = unpack2(acc2[p][1]);
        float2 u2 = unpack2(acc2[p][2]);
        float2 u3 = unpack2(acc2[p][3]);
        o0.x = u0.x + bvv[0]; o0.y = u1.x + bvv[1]; o0.z = u2.x + bvv[2]; o0.w = u3.x + bvv[3];
        o1.x = u0.y + bvv[0]; o1.y = u1.y + bvv[1]; o1.z = u2.y + bvv[2]; o1.w = u3.y + bvv[3];
        *(float4*)&C[(size_t)(m0 + ty8 + 2 * p)     * N + n0 + tx4] = o0;
        *(float4*)&C[(size_t)(m0 + ty8 + 2 * p + 1) * N + n0 + tx4] = o1;
    }
}

// =====================================================================
// Recurrent LSTM scan v11: HMMA + DSMEM publish (R16) + dual-stream
// 1-lag software pipeline over the split cluster barrier.
//   Streams: A = batches 0-7 (nt0 frag slots), B = batches 8-15 (nt1).
//   Each half: 48 MMAs (16kt x 3 split-terms) + gates + DSMEM publish.
//   Schedule (1 outstanding arrive max -- legal on the single HW
//   cluster barrier):
//     A(0); ARR;  B(0); WAIT; ARR;
//     t=1..511:  A(t); WAIT; ARR;   B(t); WAIT; ARR;
//     final WAIT.
//   Each WAIT pairs an arrive issued >= one half-step earlier by all
//   peers -> barrier latency + DSMEM drain hidden behind the other
//   stream's compute. Stream slots never alias (nt0 vs nt1 words);
//   same-stream WAR is protected by the arrive/wait pairing (a peer's
//   publish of step t is gated behind our arrive of t-1, which follows
//   our fragment reads of t-1).
// =====================================================================
#define PE 132
#define AFH_OFF  0
#define AFL_OFF  65536
#define BFH_OFF  131072              // 2 buffers x 8192 B
#define BFL_OFF  147456              // 2 buffers x 8192 B
#define EX_OFF   163840
#define REC_SMEM (EX_OFF + 16 * PE * 4)   // 172288 B

#define CARR()  asm volatile("barrier.cluster.arrive.aligned;" ::: "memory")
#define CWAIT() asm volatile("barrier.cluster.wait.aligned;"   ::: "memory")

__device__ __forceinline__ uint32_t smem_u32(const void* p) {
    uint32_t a;
    asm("{ .reg .u64 t; cvta.to.shared.u64 t, %1; cvt.u32.u64 %0, t; }"
        : "=r"(a) : "l"(p));
    return a;
}
__device__ __forceinline__ uint32_t bfpack(float a, float b) {
    __nv_bfloat162 t = __floats2bfloat162_rn(a, b);
    return *reinterpret_cast<uint32_t*>(&t);
}
__device__ __forceinline__ void mma_bf16(float& c0, float& c1, float& c2, float& c3,
                                         uint32_t a0, uint32_t a1, uint32_t a2, uint32_t a3,
                                         uint32_t b0, uint32_t b1) {
    asm volatile(
        "mma.sync.aligned.m16n8k16.row.col.f32.bf16.bf16.f32 "
        "{%0,%1,%2,%3}, {%4,%5,%6,%7}, {%8,%9}, {%0,%1,%2,%3};"
        : "+f"(c0), "+f"(c1), "+f"(c2), "+f"(c3)
        : "r"(a0), "r"(a1), "r"(a2), "r"(a3), "r"(b0), "r"(b1));
}
__device__ __forceinline__ void st_cluster_u32(uint32_t laddr, int rrank, uint32_t val) {
    uint32_t ra;
    asm("mapa.shared::cluster.u32 %0, %1, %2;" : "=r"(ra) : "r"(laddr), "r"(rrank));
    asm volatile("st.shared::cluster.u32 [%0], %1;" :: "r"(ra), "r"(val) : "memory");
}
__device__ __forceinline__ float fsig(float x) {
    x = fminf(fmaxf(x, -30.f), 30.f);
    return __fdividef(1.f, 1.f + __expf(-x));
}
__device__ __forceinline__ float ftanh_(float x) {
    x = fminf(fmaxf(x, -15.f), 15.f);
    float e = __expf(-2.f * x);
    return __fdividef(1.f - e, 1.f + e);
}

// One stream's half-step: MMA (48) + ex scatter + gates + publish.
__device__ __forceinline__ void rec_half(
    int t, int u, char* smem, const uint32_t* AFH, const uint32_t* AFL,
    float* ex, uint32_t smb,
    int tid, int w, int lane, int gid, int ctib, int rank, int b0,
    const float* __restrict__ xpg, float* __restrict__ seq_out, float& cst)
{
    const int b = (tid >> 5) + (u << 3);   // this thread's batch (gates)

    // xp prefetch (independent of h)
    float xv[4];
#pragma unroll
    for (int g = 0; g < 4; ++g)
        xv[g] = __ldg(&xpg[((size_t)(b0 + b) * T_ + t) * G_ +
                           (g << 8) + (rank << 5) + lane]);

    // MMA over this stream's nt slot
    const uint32_t* BH = (const uint32_t*)(smem + BFH_OFF + ((t & 1) << 13));
    const uint32_t* BL = (const uint32_t*)(smem + BFL_OFF + ((t & 1) << 13));
    float c[4] = {0.f, 0.f, 0.f, 0.f};
#pragma unroll
    for (int kt = 0; kt < 16; ++kt) {
        uint4 Ah = ((const uint4*)AFH)[(w << 4 | kt) * 32 + lane];
        uint4 Al = ((const uint4*)AFL)[(w << 4 | kt) * 32 + lane];
        uint2 Bh = ((const uint2*)BH)[((kt << 1) | u) * 32 + lane];
        uint2 Bl = ((const uint2*)BL)[((kt << 1) | u) * 32 + lane];
        mma_bf16(c[0], c[1], c[2], c[3], Ah.x, Ah.y, Ah.z, Ah.w, Bh.x, Bh.y);
        mma_bf16(c[0], c[1], c[2], c[3], Ah.x, Ah.y, Ah.z, Ah.w, Bl.x, Bl.y);
        mma_bf16(c[0], c[1], c[2], c[3], Al.x, Al.y, Al.z, Al.w, Bh.x, Bh.y);
    }

    // scatter D frags to ex rows of this stream (disjoint from other stream)
    {
        int r  = (w << 4) + gid;
        int ba = (u << 3) + (ctib << 1);
        ex[(ba)     * PE + r]     = c[0];
        ex[(ba + 1) * PE + r]     = c[1];
        ex[(ba)     * PE + r + 8] = c[2];
        ex[(ba + 1) * PE + r + 8] = c[3];
    }
    __syncthreads();

    // gates + state + h write + DSMEM publish (into buf (t+1)&1, slot u)
    const uint32_t nbuf = ((t + 1) & 1) << 13;
    {
        float iv = ex[b * PE + lane]      + xv[0];
        float fv = ex[b * PE + 32 + lane] + xv[1];
        float gv = ex[b * PE + 64 + lane] + xv[2];
        float ov = ex[b * PE + 96 + lane] + xv[3];
        float ig = fsig(iv), fg = fsig(fv), gg = ftanh_(gv), og = fsig(ov);
        cst = fg * cst + ig * gg;
        float hval = og * ftanh_(cst);
        seq_out[((size_t)(b0 + b) * T_ + t) * H_ + (rank << 5) + lane] = hval;

        __nv_bfloat16 bh = __float2bfloat16(hval);
        float rem = hval - __bfloat162float(bh);
        __nv_bfloat16 bl = __float2bfloat16(rem);
        uint32_t own = (uint32_t)__bfloat16_as_ushort(bh) |
                       ((uint32_t)__bfloat16_as_ushort(bl) << 16);
        uint32_t nb = __shfl_down_sync(0xffffffffu, own, 1);
        uint32_t hw = (own & 0xffffu) | (nb << 16);          // (hi_even, hi_odd)
        uint32_t lw = (own >> 16) | (nb & 0xffff0000u);      // (lo_even, lo_odd)
        uint32_t lw_o = __shfl_up_sync(0xffffffffu, lw, 1);  // deliver to odd lane

        int kglob = (rank << 5) + (lane & 30);
        int kt2 = kglob >> 4;
        int jp  = (kglob & 15) >> 1;
        int fidx = (((kt2 << 1) + u) << 6) +
                   ((((b & 7) << 2) + (jp & 3)) << 1) + (jp >> 2);
        uint32_t val, laddr;
        if (lane & 1) { val = lw_o; laddr = smb + BFL_OFF + nbuf + (fidx << 2); }
        else          { val = hw;   laddr = smb + BFH_OFF + nbuf + (fidx << 2); }
#pragma unroll
        for (int rr = 0; rr < 8; ++rr) st_cluster_u32(laddr, rr, val);
    }
}

__global__ void __cluster_dims__(8, 1, 1) __launch_bounds__(256, 1)
lstm_rec(const float* __restrict__ Whh, const float* __restrict__ xpg,
         float* __restrict__ seq_out)
{
    extern __shared__ __align__(16) char smem[];
    uint32_t* AFH = (uint32_t*)(smem + AFH_OFF);   // [8w][16kt][32lane][4reg]
    uint32_t* AFL = (uint32_t*)(smem + AFL_OFF);
    float*    ex  = (float*)(smem + EX_OFF);       // [16 b][PE rows]

    const int tid  = threadIdx.x;
    const int w    = tid >> 5;
    const int lane = tid & 31;
    const int gid  = lane >> 2;
    const int ctib = lane & 3;
    const int rank = blockIdx.x & 7;
    const int b0   = (blockIdx.x >> 3) * 16;
    const uint32_t smb = smem_u32(smem);

    // ---- build W fragment arrays once (hi/lo bf16 split) ----
    for (int i = tid; i < 16384; i += 256) {
        int reg = i & 3, ln = (i >> 2) & 31, kt = (i >> 7) & 15, ww = i >> 11;
        int g = ln >> 2, cb = ln & 3;
        int m  = ww * 16 + g + ((reg & 1) << 3);
        int k0 = kt * 16 + cb * 2 + ((reg >> 1) << 3);
        int gr = ((m >> 5) << 8) + (rank << 5) + (m & 31);
        float w0 = __ldg(&Whh[(size_t)gr * H_ + k0]);
        float w1 = __ldg(&Whh[(size_t)gr * H_ + k0 + 1]);
        __nv_bfloat16 h0 = __float2bfloat16(w0);
        __nv_bfloat16 h1 = __float2bfloat16(w1);
        AFH[i] = bfpack(__bfloat162float(h0), __bfloat162float(h1));
        AFL[i] = bfpack(w0 - __bfloat162float(h0), w1 - __bfloat162float(h1));
    }
    // zero B frag buffer 0 ONLY (t=0 state; buffer 1 is written by
    // peers' t=0 publishes and must not be touched here)
    for (int i = tid; i < 2048; i += 256) {
        ((uint32_t*)(smem + BFH_OFF))[i] = 0u;
        ((uint32_t*)(smem + BFL_OFF))[i] = 0u;
    }

    float cstA = 0.f, cstB = 0.f;
    __syncthreads();

    // ---- prime (t = 0): both streams start from h = 0 (buf0 zeroed) ----
    rec_half(0, 0, smem, AFH, AFL, ex, smb, tid, w, lane, gid, ctib, rank, b0,
             xpg, seq_out, cstA);
    CARR();                       // release A(0) publishes
    rec_half(0, 1, smem, AFH, AFL, ex, smb, tid, w, lane, gid, ctib, rank, b0,
             xpg, seq_out, cstB);
    CWAIT();                      // pairs arr_A(0) (stale by a half-step)
    CARR();                       // release B(0) publishes

    // ---- steady state: each wait pairs an arrive >= one half-step old ----
    for (int t = 1; t < T_; ++t) {
        rec_half(t, 0, smem, AFH, AFL, ex, smb, tid, w, lane, gid, ctib, rank, b0,
                 xpg, seq_out, cstA);
        CWAIT();                  // pairs arr_B(t-1) (stale)
        CARR();                   // release A(t)
        rec_half(t, 1, smem, AFH, AFL, ex, smb, tid, w, lane, gid, ctib, rank, b0,
                 xpg, seq_out, cstB);
        CWAIT();                  // pairs arr_A(t) (issued a half-step ago)
        CARR();                   // release B(t)
    }
    CWAIT();                      // balance final arrive
}

// =====================================================================
// Launcher
// =====================================================================
extern "C" void kernel_launch(void* const* d_in, const int* in_sizes, int n_in,
                              void* d_out, int out_size)
{
    const float* x     = (const float*)d_in[0];
    const float* eWih0 = (const float*)d_in[1];
    const float* eWhh0 = (const float*)d_in[2];
    const float* ebih0 = (const float*)d_in[3];
    const float* ebhh0 = (const float*)d_in[4];
    const float* eWih1 = (const float*)d_in[5];
    const float* eWhh1 = (const float*)d_in[6];
    const float* ebih1 = (const float*)d_in[7];
    const float* ebhh1 = (const float*)d_in[8];
    const float* dWih0 = (const float*)d_in[9];
    const float* dWhh0 = (const float*)d_in[10];
    const float* dbih0 = (const float*)d_in[11];
    const float* dbhh0 = (const float*)d_in[12];
    const float* dWih1 = (const float*)d_in[13];
    const float* dWhh1 = (const float*)d_in[14];
    const float* dbih1 = (const float*)d_in[15];
    const float* dbhh1 = (const float*)d_in[16];
    const float* out_W = (const float*)d_in[17];
    const float* out_b = (const float*)d_in[18];
    float* out = (float*)d_out;

    void* p;
    cudaGetSymbolAddress(&p, g_xp); float* xp = (float*)p;
    cudaGetSymbolAddress(&p, g_s0); float* s0 = (float*)p;
    cudaGetSymbolAddress(&p, g_s1); float* s1 = (float*)p;

    cudaFuncSetAttribute(lstm_rec, cudaFuncAttributeMaxDynamicSharedMemorySize, REC_SMEM);

    dim3 blk(256);
    dim3 gXP(G_ / 64, BT_ / 128);   // N=1024 tiles x M tiles
    dim3 gPR(I_ / 64, BT_ / 128);   // projection N=64

    // encoder layer 0 (K = I = 64)
    gemm_abt_bias<<<gXP, blk>>>(x, eWih0, ebih0, ebhh0, xp, BT_, G_, I_);
    lstm_rec<<<128, blk, REC_SMEM>>>(eWhh0, xp, s0);
    // encoder layer 1 (K = H)
    gemm_abt_bias<<<gXP, blk>>>(s0, eWih1, ebih1, ebhh1, xp, BT_, G_, H_);
    lstm_rec<<<128, blk, REC_SMEM>>>(eWhh1, xp, s1);
    // decoder layer 0
    gemm_abt_bias<<<gXP, blk>>>(s1, dWih0, dbih0, dbhh0, xp, BT_, G_, H_);
    lstm_rec<<<128, blk, REC_SMEM>>>(dWhh0, xp, s0);
    // decoder layer 1
    gemm_abt_bias<<<gXP, blk>>>(s0, dWih1, dbih1, dbhh1, xp, BT_, G_, H_);
    lstm_rec<<<128, blk, REC_SMEM>>>(dWhh1, xp, s1);
    // output projection (N = I = 64, K = H)
    gemm_abt_bias<<<gPR, blk>>>(s1, out_W, out_b, nullptr, out, BT_, I_, H_);
}